// round 12
// baseline (speedup 1.0000x reference)
#include <cuda_runtime.h>
#include <cstdint>

#define D_IN      1280
#define H_DIM     64
#define BM        64
#define BK        16
#define NSTAGE    5
#define KT        (D_IN / BK)                 // 80
#define XS_STRIDE 20                          // banks (20g+t)%32 all-distinct for frag LDS
#define STAGE_FLOATS ((BM + H_DIM) * XS_STRIDE)   // 128*20 = 2560 floats = 10240 B
#define HS_STRIDE 65

// W1 pre-rounded to tf32-RNA (bits exact under the MMA's tf32 read)
__device__ float g_w1t[H_DIM * D_IN];

// ---------------- PTX helpers ----------------
__device__ __forceinline__ void cp16(void* dst, const void* src) {
    unsigned s = (unsigned)__cvta_generic_to_shared(dst);
    asm volatile("cp.async.cg.shared.global [%0], [%1], 16;\n" :: "r"(s), "l"(src));
}
__device__ __forceinline__ void cp_commit() { asm volatile("cp.async.commit_group;\n"); }
template<int N> __device__ __forceinline__ void cp_wait() {
    asm volatile("cp.async.wait_group %0;\n" :: "n"(N));
}
__device__ __forceinline__ unsigned f2tf(float f) {
    unsigned r; asm("cvt.rna.tf32.f32 %0, %1;\n" : "=r"(r) : "f"(f)); return r;
}
__device__ __forceinline__ void mma8(float& c0, float& c1, float& c2, float& c3,
                                     unsigned a0, unsigned a1, unsigned a2, unsigned a3,
                                     unsigned b0, unsigned b1) {
    asm volatile("mma.sync.aligned.m16n8k8.row.col.f32.tf32.tf32.f32 "
                 "{%0,%1,%2,%3}, {%4,%5,%6,%7}, {%8,%9}, {%0,%1,%2,%3};\n"
                 : "+f"(c0), "+f"(c1), "+f"(c2), "+f"(c3)
                 : "r"(a0), "r"(a1), "r"(a2), "r"(a3), "r"(b0), "r"(b1));
}

// ---------------- W1 -> tf32-RNA scratch ----------------
__global__ void prep_w1_kernel(const float* __restrict__ W1) {
    int i = blockIdx.x * blockDim.x + threadIdx.x;
    if (i < H_DIM * D_IN) g_w1t[i] = __uint_as_float(f2tf(W1[i]));
}

// ---------------- fused kernel ----------------
// h = relu(x@W1^T+b1); h = h*scale+shift (BN eval); xq = tanh(h@W2^T+b2);
// 4-qubit sim with angles pi*tanh(xq); out = z@W3^T+b3.
__global__ __launch_bounds__(128, 4)
void qh_fused_kernel(const float* __restrict__ x,
                     const float* __restrict__ b1,  const float* __restrict__ bn_g,
                     const float* __restrict__ bn_b,const float* __restrict__ bn_m,
                     const float* __restrict__ bn_v,const float* __restrict__ W2,
                     const float* __restrict__ b2,  const float* __restrict__ qw,
                     const float* __restrict__ W3,  const float* __restrict__ b3,
                     float* __restrict__ out, int B)
{
    extern __shared__ float smem[];     // NSTAGE stages; reused as h-tile in epilogue
    __shared__ float bias_s[64], scale_s[64], shift_s[64];
    __shared__ float w2s[256], b2s[4], w3s[40], b3s[10];
    __shared__ float ryc[8], rys[8], rzc[8], rzs[8];

    const int tid = threadIdx.x;
    const int blockRow = blockIdx.x * BM;

    // ---- per-block parameter prep (tiny) ----
    if (tid < 64) {
        float rs = rsqrtf(bn_v[tid] + 1e-5f);
        float sc = bn_g[tid] * rs;
        scale_s[tid] = sc;
        shift_s[tid] = bn_b[tid] - bn_m[tid] * sc;
        bias_s[tid]  = b1[tid];
    }
    for (int i = tid; i < 256; i += 128) w2s[i] = W2[i];
    if (tid < 16) {
        int l = (tid >> 2) & 1, qi = tid & 3, isRz = tid >> 3;
        float half = 0.5f * qw[l * 8 + qi * 2 + isRz];
        float sv, cv; sincosf(half, &sv, &cv);
        if (isRz) { rzc[l*4+qi] = cv; rzs[l*4+qi] = sv; }
        else      { ryc[l*4+qi] = cv; rys[l*4+qi] = sv; }
    }
    if (tid < 40) w3s[tid] = W3[tid];
    if (tid < 10) b3s[tid] = b3[tid];
    if (tid < 4)  b2s[tid] = b2[tid];

    // ---- async-pipelined tf32 GEMM: [BM x 64] += x-tile @ W1-tile^T ----
    auto prefetch = [&](int kt) {
        if (kt < KT) {
            float* xs = smem + (kt % NSTAGE) * STAGE_FLOATS;
            float* ws = xs + BM * XS_STRIDE;
            const int k0 = kt * BK;
            #pragma unroll
            for (int i = 0; i < 2; i++) {           // x tile: 64 rows x 16 cols (4 chunks/row)
                int c = i * 128 + tid;
                int row = c >> 2, ch = c & 3;
                int gr = blockRow + row; if (gr >= B) gr = B - 1;
                cp16(&xs[row * XS_STRIDE + ch * 4], &x[(size_t)gr * D_IN + k0 + ch * 4]);
            }
            #pragma unroll
            for (int i = 0; i < 2; i++) {           // W1(tf32) tile: 64 rows x 16 cols
                int c = i * 128 + tid;
                int row = c >> 2, ch = c & 3;
                cp16(&ws[row * XS_STRIDE + ch * 4], &g_w1t[(size_t)row * D_IN + k0 + ch * 4]);
            }
        }
        cp_commit();
    };

    const int lane = tid & 31, warp = tid >> 5;   // 4 warps, each a 16-row band x full N=64
    const int g = lane >> 2, t = lane & 3;

    float acc[8][4];
    #pragma unroll
    for (int nt = 0; nt < 8; nt++)
        #pragma unroll
        for (int k = 0; k < 4; k++) acc[nt][k] = 0.f;

    #pragma unroll
    for (int i = 0; i < NSTAGE - 1; i++) prefetch(i);

    for (int kt = 0; kt < KT; kt++) {
        cp_wait<NSTAGE - 2>();
        __syncthreads();
        prefetch(kt + NSTAGE - 1);

        const float* xs = smem + (kt % NSTAGE) * STAGE_FLOATS;
        const float* ws = xs + BM * XS_STRIDE;
        const float* arow = xs + (warp * 16 + g) * XS_STRIDE + t;
        const float* brow = ws + g * XS_STRIDE + t;

        #pragma unroll
        for (int k8 = 0; k8 < BK / 8; k8++) {
            const int kb = k8 * 8;
            unsigned a[4], b[8][2];
            a[0] = f2tf(arow[kb]);
            a[1] = f2tf(arow[8 * XS_STRIDE + kb]);
            a[2] = f2tf(arow[kb + 4]);
            a[3] = f2tf(arow[8 * XS_STRIDE + kb + 4]);
            #pragma unroll
            for (int nt = 0; nt < 8; nt++) {        // W1 pre-rounded: raw bits == tf32-RNA
                const float* p = brow + nt * 8 * XS_STRIDE + kb;
                b[nt][0] = __float_as_uint(p[0]);
                b[nt][1] = __float_as_uint(p[4]);
            }
            #pragma unroll
            for (int nt = 0; nt < 8; nt++)
                mma8(acc[nt][0], acc[nt][1], acc[nt][2], acc[nt][3],
                     a[0], a[1], a[2], a[3], b[nt][0], b[nt][1]);
        }
    }
    __syncthreads();   // all warps done reading stage buffers

    // ---- epilogue: bias+relu+BN, stage h-tile to smem ----
    float* hs = smem;  // [BM][HS_STRIDE] overlay (16.6 KB < 51.2 KB pipeline buffers)
    {
        const int r0 = warp * 16 + g;
        #pragma unroll
        for (int nt = 0; nt < 8; nt++) {
            const int n0 = nt * 8 + t * 2;
            float s0 = scale_s[n0],  s1 = scale_s[n0 + 1];
            float f0 = shift_s[n0],  f1 = shift_s[n0 + 1];
            float bi0 = bias_s[n0],  bi1 = bias_s[n0 + 1];
            hs[r0 * HS_STRIDE + n0]           = fmaxf(acc[nt][0] + bi0, 0.f) * s0 + f0;
            hs[r0 * HS_STRIDE + n0 + 1]       = fmaxf(acc[nt][1] + bi1, 0.f) * s1 + f1;
            hs[(r0 + 8) * HS_STRIDE + n0]     = fmaxf(acc[nt][2] + bi0, 0.f) * s0 + f0;
            hs[(r0 + 8) * HS_STRIDE + n0 + 1] = fmaxf(acc[nt][3] + bi1, 0.f) * s1 + f1;
        }
    }
    __syncthreads();

    // ---- one thread per row: W2 proj + 4-qubit statevector sim + W3 out ----
    const int gr = blockRow + tid;
    if (tid < BM && gr < B) {
        float aq0 = b2s[0], aq1 = b2s[1], aq2 = b2s[2], aq3 = b2s[3];
        const float* hr = hs + tid * HS_STRIDE;
        #pragma unroll
        for (int j = 0; j < 64; j++) {
            float v = hr[j];
            aq0 += v * w2s[j];        aq1 += v * w2s[64 + j];
            aq2 += v * w2s[128 + j];  aq3 += v * w2s[192 + j];
        }
        float aq[4] = {aq0, aq1, aq2, aq3};
        float ci[4], si[4];
        #pragma unroll
        for (int i = 0; i < 4; i++) {
            // half-angle = (pi/2) * tanh(tanh(pre))  (double tanh is faithful to reference)
            float hl = 1.57079632679489662f * tanhf(tanhf(aq[i]));
            sincosf(hl, &si[i], &ci[i]);
        }
        // initial RY layer on |0000>: real product state. bit of wire i = (s >> (3-i)) & 1
        float re[16], im[16];
        #pragma unroll
        for (int s = 0; s < 16; s++) {
            float p = ((s >> 3) & 1 ? si[0] : ci[0]);
            p *=      ((s >> 2) & 1 ? si[1] : ci[1]);
            p *=      ((s >> 1) & 1 ? si[2] : ci[2]);
            p *=      ((s     ) & 1 ? si[3] : ci[3]);
            re[s] = p; im[s] = 0.f;
        }
        #pragma unroll
        for (int l = 0; l < 2; l++) {
            #pragma unroll
            for (int qi = 0; qi < 4; qi++) {
                const int m = 1 << (3 - qi);
                float c = ryc[l * 4 + qi], sv = rys[l * 4 + qi];
                #pragma unroll
                for (int s0 = 0; s0 < 16; s0++) {
                    if (!(s0 & m)) {
                        const int s1 = s0 | m;
                        float r0 = re[s0], r1 = re[s1], i0 = im[s0], i1 = im[s1];
                        re[s0] = c * r0 - sv * r1;  im[s0] = c * i0 - sv * i1;
                        re[s1] = sv * r0 + c * r1;  im[s1] = sv * i0 + c * i1;
                    }
                }
                float ch = rzc[l * 4 + qi], sh = rzs[l * 4 + qi];
                #pragma unroll
                for (int s0 = 0; s0 < 16; s0++) {
                    float r = re[s0], iz = im[s0];
                    if (!(s0 & m)) { re[s0] = r * ch + iz * sh; im[s0] = iz * ch - r * sh; }
                    else           { re[s0] = r * ch - iz * sh; im[s0] = iz * ch + r * sh; }
                }
            }
            #pragma unroll
            for (int qi = 0; qi < 4; qi++) {        // CNOT(qi, (qi+1)%4), in order
                const int mc = 1 << (3 - qi);
                const int mt_ = 1 << (3 - ((qi + 1) & 3));
                #pragma unroll
                for (int s0 = 0; s0 < 16; s0++) {
                    if ((s0 & mc) && !(s0 & mt_)) {
                        const int s1 = s0 | mt_;
                        float tr = re[s0]; re[s0] = re[s1]; re[s1] = tr;
                        float ti = im[s0]; im[s0] = im[s1]; im[s1] = ti;
                    }
                }
            }
        }
        float z0 = 0.f, z1 = 0.f, z2 = 0.f, z3 = 0.f;
        #pragma unroll
        for (int s = 0; s < 16; s++) {
            float p = re[s] * re[s] + im[s] * im[s];
            z0 += (s & 8) ? -p : p;
            z1 += (s & 4) ? -p : p;
            z2 += (s & 2) ? -p : p;
            z3 += (s & 1) ? -p : p;
        }
        #pragma unroll
        for (int c = 0; c < 10; c++) {
            out[(size_t)gr * 10 + c] = b3s[c] + w3s[c * 4 + 0] * z0 + w3s[c * 4 + 1] * z1
                                              + w3s[c * 4 + 2] * z2 + w3s[c * 4 + 3] * z3;
        }
    }
}

// ---------------- launch ----------------
extern "C" void kernel_launch(void* const* d_in, const int* in_sizes, int n_in,
                              void* d_out, int out_size) {
    const float* x    = (const float*)d_in[0];
    const float* W1   = (const float*)d_in[1];
    const float* b1   = (const float*)d_in[2];
    const float* bn_g = (const float*)d_in[3];
    const float* bn_b = (const float*)d_in[4];
    const float* bn_m = (const float*)d_in[5];
    const float* bn_v = (const float*)d_in[6];
    const float* W2   = (const float*)d_in[7];
    const float* b2   = (const float*)d_in[8];
    const float* qw   = (const float*)d_in[9];
    const float* W3   = (const float*)d_in[10];
    const float* b3   = (const float*)d_in[11];
    float* out = (float*)d_out;

    const int B = in_sizes[0] / D_IN;
    const int grid = (B + BM - 1) / BM;   // 512
    const size_t smem_bytes = (size_t)NSTAGE * STAGE_FLOATS * sizeof(float); // 51200 B

    prep_w1_kernel<<<(H_DIM * D_IN + 255) / 256, 256>>>(W1);

    cudaFuncSetAttribute(qh_fused_kernel,
                         cudaFuncAttributeMaxDynamicSharedMemorySize, (int)smem_bytes);
    qh_fused_kernel<<<grid, 128, smem_bytes>>>(x, b1, bn_g, bn_b, bn_m, bn_v,
                                               W2, b2, qw, W3, b3, out, B);
}

// round 14
// speedup vs baseline: 1.2401x; 1.2401x over previous
#include <cuda_runtime.h>
#include <cstdint>

#define D_IN      1280
#define H_DIM     64
#define BM        112
#define BK        32
#define NSTAGE    3
#define NTHREADS  224
#define KT        (D_IN / BK)                 // 40
#define XS_STRIDE 36                          // banks (4g+t)%32 all-distinct for frag LDS
#define STAGE_FLOATS ((BM + H_DIM) * XS_STRIDE)   // 176*36 = 6336 floats = 25344 B
#define HS_STRIDE 65

// W1 pre-rounded to tf32-RNA (bits exact under the MMA's tf32 read)
__device__ float g_w1t[H_DIM * D_IN];

// ---------------- PTX helpers ----------------
__device__ __forceinline__ void cp16(void* dst, const void* src) {
    unsigned s = (unsigned)__cvta_generic_to_shared(dst);
    asm volatile("cp.async.cg.shared.global [%0], [%1], 16;\n" :: "r"(s), "l"(src));
}
__device__ __forceinline__ void cp_commit() { asm volatile("cp.async.commit_group;\n"); }
template<int N> __device__ __forceinline__ void cp_wait() {
    asm volatile("cp.async.wait_group %0;\n" :: "n"(N));
}
__device__ __forceinline__ unsigned f2tf(float f) {
    unsigned r; asm("cvt.rna.tf32.f32 %0, %1;\n" : "=r"(r) : "f"(f)); return r;
}
__device__ __forceinline__ void mma8(float& c0, float& c1, float& c2, float& c3,
                                     unsigned a0, unsigned a1, unsigned a2, unsigned a3,
                                     unsigned b0, unsigned b1) {
    asm volatile("mma.sync.aligned.m16n8k8.row.col.f32.tf32.tf32.f32 "
                 "{%0,%1,%2,%3}, {%4,%5,%6,%7}, {%8,%9}, {%0,%1,%2,%3};\n"
                 : "+f"(c0), "+f"(c1), "+f"(c2), "+f"(c3)
                 : "r"(a0), "r"(a1), "r"(a2), "r"(a3), "r"(b0), "r"(b1));
}

// ---------------- W1 -> tf32-RNA scratch ----------------
__global__ void prep_w1_kernel(const float* __restrict__ W1) {
    int i = blockIdx.x * blockDim.x + threadIdx.x;
    if (i < H_DIM * D_IN) g_w1t[i] = __uint_as_float(f2tf(W1[i]));
}

// ---------------- fused kernel ----------------
// h = relu(x@W1^T+b1); h = h*scale+shift (BN eval); xq = tanh(h@W2^T+b2);
// 4-qubit sim with angles pi*tanh(xq); out = z@W3^T+b3.
__global__ __launch_bounds__(NTHREADS, 2)
void qh_fused_kernel(const float* __restrict__ x,
                     const float* __restrict__ b1,  const float* __restrict__ bn_g,
                     const float* __restrict__ bn_b,const float* __restrict__ bn_m,
                     const float* __restrict__ bn_v,const float* __restrict__ W2,
                     const float* __restrict__ b2,  const float* __restrict__ qw,
                     const float* __restrict__ W3,  const float* __restrict__ b3,
                     float* __restrict__ out, int B)
{
    extern __shared__ float smem[];     // NSTAGE stages; reused as h-tile in epilogue
    __shared__ float bias_s[64], scale_s[64], shift_s[64];
    __shared__ float w2s[256], b2s[4], w3s[40], b3s[10];
    __shared__ float ryc[8], rys[8], rzc[8], rzs[8];

    const int tid = threadIdx.x;
    const int blockRow = blockIdx.x * BM;

    // ---- per-block parameter prep (tiny) ----
    if (tid < 64) {
        float rs = rsqrtf(bn_v[tid] + 1e-5f);
        float sc = bn_g[tid] * rs;
        scale_s[tid] = sc;
        shift_s[tid] = bn_b[tid] - bn_m[tid] * sc;
        bias_s[tid]  = b1[tid];
    }
    for (int i = tid; i < 256; i += NTHREADS) w2s[i] = W2[i];
    if (tid < 16) {
        int l = (tid >> 2) & 1, qi = tid & 3, isRz = tid >> 3;
        float half = 0.5f * qw[l * 8 + qi * 2 + isRz];
        float sv, cv; sincosf(half, &sv, &cv);
        if (isRz) { rzc[l*4+qi] = cv; rzs[l*4+qi] = sv; }
        else      { ryc[l*4+qi] = cv; rys[l*4+qi] = sv; }
    }
    if (tid < 40) w3s[tid] = W3[tid];
    if (tid < 10) b3s[tid] = b3[tid];
    if (tid < 4)  b2s[tid] = b2[tid];

    // ---- async-pipelined tf32 GEMM: [BM x 64] += x-tile @ W1-tile^T ----
    auto prefetch = [&](int kt) {
        if (kt < KT) {
            float* xs = smem + (kt % NSTAGE) * STAGE_FLOATS;
            float* ws = xs + BM * XS_STRIDE;
            const int k0 = kt * BK;
            #pragma unroll
            for (int i = 0; i < 4; i++) {           // x tile: 112 rows x 32 cols = 896 chunks
                int c = i * NTHREADS + tid;
                int row = c >> 3, ch = c & 7;
                int gr = blockRow + row; if (gr >= B) gr = B - 1;
                cp16(&xs[row * XS_STRIDE + ch * 4], &x[(size_t)gr * D_IN + k0 + ch * 4]);
            }
            #pragma unroll
            for (int i = 0; i < 3; i++) {           // W1(tf32) tile: 64 x 32 = 512 chunks
                int c = i * NTHREADS + tid;
                if (c < 512) {
                    int row = c >> 3, ch = c & 7;
                    cp16(&ws[row * XS_STRIDE + ch * 4], &g_w1t[(size_t)row * D_IN + k0 + ch * 4]);
                }
            }
        }
        cp_commit();
    };

    const int lane = tid & 31, warp = tid >> 5;   // 7 warps, each a 16-row band x full N=64
    const int g = lane >> 2, t = lane & 3;

    float acc[8][4];
    #pragma unroll
    for (int nt = 0; nt < 8; nt++)
        #pragma unroll
        for (int k = 0; k < 4; k++) acc[nt][k] = 0.f;

    #pragma unroll
    for (int i = 0; i < NSTAGE - 1; i++) prefetch(i);

    for (int kt = 0; kt < KT; kt++) {
        cp_wait<NSTAGE - 2>();
        __syncthreads();
        prefetch(kt + NSTAGE - 1);

        const float* xs = smem + (kt % NSTAGE) * STAGE_FLOATS;
        const float* ws = xs + BM * XS_STRIDE;
        const float* arow = xs + (warp * 16 + g) * XS_STRIDE + t;
        const float* brow = ws + g * XS_STRIDE + t;

        #pragma unroll
        for (int k8 = 0; k8 < BK / 8; k8++) {
            const int kb = k8 * 8;
            unsigned a[4], b[8][2];
            a[0] = f2tf(arow[kb]);
            a[1] = f2tf(arow[8 * XS_STRIDE + kb]);
            a[2] = f2tf(arow[kb + 4]);
            a[3] = f2tf(arow[8 * XS_STRIDE + kb + 4]);
            #pragma unroll
            for (int nt = 0; nt < 8; nt++) {        // W1 pre-rounded: raw bits == tf32-RNA
                const float* p = brow + nt * 8 * XS_STRIDE + kb;
                b[nt][0] = __float_as_uint(p[0]);
                b[nt][1] = __float_as_uint(p[4]);
            }
            #pragma unroll
            for (int nt = 0; nt < 8; nt++)
                mma8(acc[nt][0], acc[nt][1], acc[nt][2], acc[nt][3],
                     a[0], a[1], a[2], a[3], b[nt][0], b[nt][1]);
        }
    }
    __syncthreads();   // all warps done reading stage buffers

    // ---- epilogue: bias+relu+BN, stage h-tile to smem ----
    float* hs = smem;  // [BM][HS_STRIDE] overlay (29.1 KB < 76 KB pipeline buffers)
    {
        const int r0 = warp * 16 + g;
        #pragma unroll
        for (int nt = 0; nt < 8; nt++) {
            const int n0 = nt * 8 + t * 2;
            float s0 = scale_s[n0],  s1 = scale_s[n0 + 1];
            float f0 = shift_s[n0],  f1 = shift_s[n0 + 1];
            float bi0 = bias_s[n0],  bi1 = bias_s[n0 + 1];
            hs[r0 * HS_STRIDE + n0]           = fmaxf(acc[nt][0] + bi0, 0.f) * s0 + f0;
            hs[r0 * HS_STRIDE + n0 + 1]       = fmaxf(acc[nt][1] + bi1, 0.f) * s1 + f1;
            hs[(r0 + 8) * HS_STRIDE + n0]     = fmaxf(acc[nt][2] + bi0, 0.f) * s0 + f0;
            hs[(r0 + 8) * HS_STRIDE + n0 + 1] = fmaxf(acc[nt][3] + bi1, 0.f) * s1 + f1;
        }
    }
    __syncthreads();

    // ---- one thread per row: W2 proj + 4-qubit statevector sim + W3 out ----
    const int gr = blockRow + tid;
    if (tid < BM && gr < B) {
        float aq0 = b2s[0], aq1 = b2s[1], aq2 = b2s[2], aq3 = b2s[3];
        const float* hr = hs + tid * HS_STRIDE;
        #pragma unroll
        for (int j = 0; j < 64; j++) {
            float v = hr[j];
            aq0 += v * w2s[j];        aq1 += v * w2s[64 + j];
            aq2 += v * w2s[128 + j];  aq3 += v * w2s[192 + j];
        }
        float aq[4] = {aq0, aq1, aq2, aq3};
        float ci[4], si[4];
        #pragma unroll
        for (int i = 0; i < 4; i++) {
            // half-angle = (pi/2) * tanh(tanh(pre))  (double tanh is faithful to reference)
            float hl = 1.57079632679489662f * tanhf(tanhf(aq[i]));
            sincosf(hl, &si[i], &ci[i]);
        }
        // initial RY layer on |0000>: real product state. bit of wire i = (s >> (3-i)) & 1
        float re[16], im[16];
        #pragma unroll
        for (int s = 0; s < 16; s++) {
            float p = ((s >> 3) & 1 ? si[0] : ci[0]);
            p *=      ((s >> 2) & 1 ? si[1] : ci[1]);
            p *=      ((s >> 1) & 1 ? si[2] : ci[2]);
            p *=      ((s     ) & 1 ? si[3] : ci[3]);
            re[s] = p; im[s] = 0.f;
        }
        #pragma unroll
        for (int l = 0; l < 2; l++) {
            #pragma unroll
            for (int qi = 0; qi < 4; qi++) {
                const int m = 1 << (3 - qi);
                float c = ryc[l * 4 + qi], sv = rys[l * 4 + qi];
                #pragma unroll
                for (int s0 = 0; s0 < 16; s0++) {
                    if (!(s0 & m)) {
                        const int s1 = s0 | m;
                        float r0 = re[s0], r1 = re[s1], i0 = im[s0], i1 = im[s1];
                        re[s0] = c * r0 - sv * r1;  im[s0] = c * i0 - sv * i1;
                        re[s1] = sv * r0 + c * r1;  im[s1] = sv * i0 + c * i1;
                    }
                }
                float ch = rzc[l * 4 + qi], sh = rzs[l * 4 + qi];
                #pragma unroll
                for (int s0 = 0; s0 < 16; s0++) {
                    float r = re[s0], iz = im[s0];
                    if (!(s0 & m)) { re[s0] = r * ch + iz * sh; im[s0] = iz * ch - r * sh; }
                    else           { re[s0] = r * ch - iz * sh; im[s0] = iz * ch + r * sh; }
                }
            }
            #pragma unroll
            for (int qi = 0; qi < 4; qi++) {        // CNOT(qi, (qi+1)%4), in order
                const int mc = 1 << (3 - qi);
                const int mt_ = 1 << (3 - ((qi + 1) & 3));
                #pragma unroll
                for (int s0 = 0; s0 < 16; s0++) {
                    if ((s0 & mc) && !(s0 & mt_)) {
                        const int s1 = s0 | mt_;
                        float tr = re[s0]; re[s0] = re[s1]; re[s1] = tr;
                        float ti = im[s0]; im[s0] = im[s1]; im[s1] = ti;
                    }
                }
            }
        }
        float z0 = 0.f, z1 = 0.f, z2 = 0.f, z3 = 0.f;
        #pragma unroll
        for (int s = 0; s < 16; s++) {
            float p = re[s] * re[s] + im[s] * im[s];
            z0 += (s & 8) ? -p : p;
            z1 += (s & 4) ? -p : p;
            z2 += (s & 2) ? -p : p;
            z3 += (s & 1) ? -p : p;
        }
        #pragma unroll
        for (int c = 0; c < 10; c++) {
            out[(size_t)gr * 10 + c] = b3s[c] + w3s[c * 4 + 0] * z0 + w3s[c * 4 + 1] * z1
                                              + w3s[c * 4 + 2] * z2 + w3s[c * 4 + 3] * z3;
        }
    }
}

// ---------------- launch ----------------
extern "C" void kernel_launch(void* const* d_in, const int* in_sizes, int n_in,
                              void* d_out, int out_size) {
    const float* x    = (const float*)d_in[0];
    const float* W1   = (const float*)d_in[1];
    const float* b1   = (const float*)d_in[2];
    const float* bn_g = (const float*)d_in[3];
    const float* bn_b = (const float*)d_in[4];
    const float* bn_m = (const float*)d_in[5];
    const float* bn_v = (const float*)d_in[6];
    const float* W2   = (const float*)d_in[7];
    const float* b2   = (const float*)d_in[8];
    const float* qw   = (const float*)d_in[9];
    const float* W3   = (const float*)d_in[10];
    const float* b3   = (const float*)d_in[11];
    float* out = (float*)d_out;

    const int B = in_sizes[0] / D_IN;
    const int grid = (B + BM - 1) / BM;   // 293
    const size_t smem_bytes = (size_t)NSTAGE * STAGE_FLOATS * sizeof(float); // 76032 B

    prep_w1_kernel<<<(H_DIM * D_IN + 255) / 256, 256>>>(W1);

    cudaFuncSetAttribute(qh_fused_kernel,
                         cudaFuncAttributeMaxDynamicSharedMemorySize, (int)smem_bytes);
    qh_fused_kernel<<<grid, NTHREADS, smem_bytes>>>(x, b1, bn_g, bn_b, bn_m, bn_v,
                                                    W2, b2, qw, W3, b3, out, B);
}